// round 1
// baseline (speedup 1.0000x reference)
#include <cuda_runtime.h>
#include <math.h>

#define BB 2
#define NN 2048
#define DIMM 512
#define HH 8
#define DHH 64
#define KNN 32
#define SCALE 0.125f
#define M_TOT (BB*NN)   // 4096

// Scratch (allocation-free rule: __device__ globals)
__device__ float g_q[BB*HH*NN*DHH];      // (b,h,n,d)
__device__ float g_k[BB*NN*DHH];         // (b,n,d)
__device__ float g_v[BB*NN*DHH];
__device__ float g_local[BB*HH*NN*DHH];  // (b,h,n,d)
__device__ float g_comb[BB*NN*HH*DHH];   // (b,n,h*64+d)

// ---------------------------------------------------------------------------
// K1: fused QKV projection.  Y[4096 x 640] = x[4096 x 512] @ [Wq | Wkv]
// BM=64, BN=64, BK=16, 256 threads, 4x4 micro-tile per thread.
// ---------------------------------------------------------------------------
__global__ void qkv_kernel(const float* __restrict__ x,
                           const float* __restrict__ Wq,
                           const float* __restrict__ Wkv) {
    __shared__ float As[64][17];
    __shared__ float Bs[16][65];
    int n0 = blockIdx.x * 64;     // 0..576 (10 tiles over 640 cols)
    int m0 = blockIdx.y * 64;     // 0..4032
    int tid = threadIdx.x;
    int ty = tid >> 4, tx = tid & 15;
    float acc[4][4] = {};
    for (int k0 = 0; k0 < DIMM; k0 += 16) {
        #pragma unroll
        for (int l = 0; l < 4; l++) {
            int e = tid + l * 256; int r = e >> 4, c = e & 15;
            As[r][c] = x[(size_t)(m0 + r) * DIMM + k0 + c];
        }
        #pragma unroll
        for (int l = 0; l < 4; l++) {
            int e = tid + l * 256; int r = e >> 6, c = e & 63;
            int j = n0 + c;
            Bs[r][c] = (j < 512) ? Wq[(size_t)(k0 + r) * 512 + j]
                                 : Wkv[(size_t)(k0 + r) * 128 + (j - 512)];
        }
        __syncthreads();
        #pragma unroll
        for (int kk = 0; kk < 16; kk++) {
            float a[4], bb[4];
            #pragma unroll
            for (int i = 0; i < 4; i++) a[i] = As[ty * 4 + i][kk];
            #pragma unroll
            for (int j = 0; j < 4; j++) bb[j] = Bs[kk][tx * 4 + j];
            #pragma unroll
            for (int i = 0; i < 4; i++)
                #pragma unroll
                for (int j = 0; j < 4; j++) acc[i][j] += a[i] * bb[j];
        }
        __syncthreads();
    }
    #pragma unroll
    for (int i = 0; i < 4; i++) {
        int m = m0 + ty * 4 + i;
        int b = m / NN, n = m % NN;
        #pragma unroll
        for (int j = 0; j < 4; j++) {
            int col = n0 + tx * 4 + j;
            float val = acc[i][j];
            if (col < 512) {
                int h = col >> 6, d = col & 63;
                g_q[(((size_t)(b * HH + h) * NN) + n) * DHH + d] = val;
            } else if (col < 576) {
                g_k[(size_t)m * DHH + (col - 512)] = val;
            } else {
                g_v[(size_t)m * DHH + (col - 576)] = val;
            }
        }
    }
}

// ---------------------------------------------------------------------------
// K2: local causal flash attention, fp32.  One block = 64 query rows of one
// (b,h).  Dynamic smem: Q/K/V/P tiles 64x65 each (~65KB).
// ---------------------------------------------------------------------------
extern __shared__ float s_dyn[];
__global__ void local_attn_kernel() {
    float* Qs = s_dyn;
    float* Ks = Qs + 64 * 65;
    float* Vs = Ks + 64 * 65;
    float* Ps = Vs + 64 * 65;
    int bh = blockIdx.y; int b = bh / HH;
    int i0 = blockIdx.x * 64;
    int tid = threadIdx.x; int ty = tid >> 4, tx = tid & 15;

    const float* qbase = g_q + (size_t)bh * NN * DHH;
    #pragma unroll
    for (int l = 0; l < 16; l++) {
        int e = tid + l * 256; int r = e >> 6, c = e & 63;
        Qs[r * 65 + c] = qbase[(size_t)(i0 + r) * DHH + c];
    }
    float m_i[4], l_i[4], acc[4][4];
    #pragma unroll
    for (int i = 0; i < 4; i++) {
        m_i[i] = -1e30f; l_i[i] = 0.f;
        #pragma unroll
        for (int j = 0; j < 4; j++) acc[i][j] = 0.f;
    }
    __syncthreads();

    const float* kbase = g_k + (size_t)b * NN * DHH;
    const float* vbase = g_v + (size_t)b * NN * DHH;
    for (int j0 = 0; j0 <= i0; j0 += 64) {
        #pragma unroll
        for (int l = 0; l < 16; l++) {
            int e = tid + l * 256; int r = e >> 6, c = e & 63;
            Ks[r * 65 + c] = kbase[(size_t)(j0 + r) * DHH + c];
            Vs[r * 65 + c] = vbase[(size_t)(j0 + r) * DHH + c];
        }
        __syncthreads();

        float s[4][4];
        #pragma unroll
        for (int i = 0; i < 4; i++)
            #pragma unroll
            for (int j = 0; j < 4; j++) s[i][j] = 0.f;
        #pragma unroll
        for (int kk = 0; kk < 64; kk++) {
            float a[4], bb[4];
            #pragma unroll
            for (int i = 0; i < 4; i++) a[i] = Qs[(ty * 4 + i) * 65 + kk];
            #pragma unroll
            for (int j = 0; j < 4; j++) bb[j] = Ks[(tx * 4 + j) * 65 + kk];
            #pragma unroll
            for (int i = 0; i < 4; i++)
                #pragma unroll
                for (int j = 0; j < 4; j++) s[i][j] += a[i] * bb[j];
        }
        bool diag = (j0 == i0);
        #pragma unroll
        for (int i = 0; i < 4; i++) {
            int row = i0 + ty * 4 + i;
            #pragma unroll
            for (int j = 0; j < 4; j++) {
                int col = j0 + tx * 4 + j;
                s[i][j] = (diag && col > row) ? -1e30f : s[i][j] * SCALE;
            }
        }
        // online softmax (row groups = 16 lanes sharing ty)
        #pragma unroll
        for (int i = 0; i < 4; i++) {
            float rm = fmaxf(fmaxf(s[i][0], s[i][1]), fmaxf(s[i][2], s[i][3]));
            #pragma unroll
            for (int o = 8; o >= 1; o >>= 1)
                rm = fmaxf(rm, __shfl_xor_sync(0xffffffffu, rm, o));
            float m_new = fmaxf(m_i[i], rm);
            float corr = __expf(m_i[i] - m_new);
            float rs = 0.f;
            #pragma unroll
            for (int j = 0; j < 4; j++) {
                float p = __expf(s[i][j] - m_new);
                s[i][j] = p; rs += p;
            }
            #pragma unroll
            for (int o = 8; o >= 1; o >>= 1)
                rs += __shfl_xor_sync(0xffffffffu, rs, o);
            l_i[i] = l_i[i] * corr + rs;
            m_i[i] = m_new;
            #pragma unroll
            for (int j = 0; j < 4; j++) acc[i][j] *= corr;
        }
        #pragma unroll
        for (int i = 0; i < 4; i++)
            #pragma unroll
            for (int j = 0; j < 4; j++)
                Ps[(ty * 4 + i) * 65 + tx * 4 + j] = s[i][j];
        __syncthreads();
        #pragma unroll 8
        for (int kk = 0; kk < 64; kk++) {
            float pv[4], vv[4];
            #pragma unroll
            for (int i = 0; i < 4; i++) pv[i] = Ps[(ty * 4 + i) * 65 + kk];
            #pragma unroll
            for (int j = 0; j < 4; j++) vv[j] = Vs[kk * 65 + tx * 4 + j];
            #pragma unroll
            for (int i = 0; i < 4; i++)
                #pragma unroll
                for (int j = 0; j < 4; j++) acc[i][j] += pv[i] * vv[j];
        }
        __syncthreads();
    }
    float* lbase = g_local + (size_t)bh * NN * DHH;
    #pragma unroll
    for (int i = 0; i < 4; i++) {
        float inv = 1.f / l_i[i];
        int row = i0 + ty * 4 + i;
        #pragma unroll
        for (int j = 0; j < 4; j++)
            lbase[(size_t)row * DHH + tx * 4 + j] = acc[i][j] * inv;
    }
}

// ---------------------------------------------------------------------------
// K3: memory attention + gate combine.  One warp per (b,h,i).
// Streams the 537 MB mem_kv once (coalesced float2), online softmax over
// 1 null slot + 32 masked memory slots.
// ---------------------------------------------------------------------------
__global__ void mem_attn_kernel(const float* __restrict__ mem_kv,
                                const float* __restrict__ mem_mask,
                                const float* __restrict__ null_k,
                                const float* __restrict__ null_v,
                                const float* __restrict__ gate) {
    int warp = (blockIdx.x * blockDim.x + threadIdx.x) >> 5;
    int lane = threadIdx.x & 31;
    if (warp >= BB * HH * NN) return;
    int i = warp % NN;
    int bh = warp / NN;
    int h = bh % HH;
    int b = bh / HH;

    float2 q2 = *(const float2*)(g_q + (size_t)warp * DHH + lane * 2);
    const float* kvbase = mem_kv + (size_t)warp * KNN * 2 * DHH;
    const float* maskbase = mem_mask + (size_t)warp * KNN;

    float m, l;
    float2 acc;
    {   // null slot, always valid
        float2 k2 = *(const float2*)(null_k + lane * 2);
        float part = q2.x * k2.x + q2.y * k2.y;
        #pragma unroll
        for (int o = 16; o >= 1; o >>= 1)
            part += __shfl_xor_sync(0xffffffffu, part, o);
        m = part * SCALE;
        l = 1.f;
        acc = *(const float2*)(null_v + lane * 2);
    }
    for (int j = 0; j < KNN; j++) {
        const float* kp = kvbase + (size_t)j * 2 * DHH;
        float2 k2 = *(const float2*)(kp + lane * 2);
        float2 v2 = *(const float2*)(kp + DHH + lane * 2);
        float part = q2.x * k2.x + q2.y * k2.y;
        #pragma unroll
        for (int o = 16; o >= 1; o >>= 1)
            part += __shfl_xor_sync(0xffffffffu, part, o);
        bool valid = (maskbase[j] != 0.0f);   // works for f32 1.0/0.0 and i32 1/0
        if (!valid) continue;                 // uniform across warp
        float s = part * SCALE;
        float m_new = fmaxf(m, s);
        float corr = __expf(m - m_new);
        float w = __expf(s - m_new);
        l = l * corr + w;
        acc.x = acc.x * corr + w * v2.x;
        acc.y = acc.y * corr + w * v2.y;
        m = m_new;
    }
    float inv = 1.f / l;
    float g = 1.f / (1.f + __expf(-gate[h]));
    float2 lv = *(const float2*)(g_local + (size_t)warp * DHH + lane * 2);
    float2 oc;
    oc.x = lv.x * g + acc.x * inv * (1.f - g);
    oc.y = lv.y * g + acc.y * inv * (1.f - g);
    float* cp = g_comb + ((size_t)(b * NN + i)) * (HH * DHH) + h * DHH;
    *(float2*)(cp + lane * 2) = oc;
}

// ---------------------------------------------------------------------------
// K4: output projection.  out[4096 x 512] = comb @ Wo + bo
// ---------------------------------------------------------------------------
__global__ void out_proj_kernel(const float* __restrict__ Wo,
                                const float* __restrict__ bo,
                                float* __restrict__ out) {
    __shared__ float As[64][17];
    __shared__ float Bs[16][65];
    int n0 = blockIdx.x * 64;
    int m0 = blockIdx.y * 64;
    int tid = threadIdx.x;
    int ty = tid >> 4, tx = tid & 15;
    float acc[4][4] = {};
    for (int k0 = 0; k0 < DIMM; k0 += 16) {
        #pragma unroll
        for (int l = 0; l < 4; l++) {
            int e = tid + l * 256; int r = e >> 4, c = e & 15;
            As[r][c] = g_comb[(size_t)(m0 + r) * DIMM + k0 + c];
        }
        #pragma unroll
        for (int l = 0; l < 4; l++) {
            int e = tid + l * 256; int r = e >> 6, c = e & 63;
            Bs[r][c] = Wo[(size_t)(k0 + r) * DIMM + n0 + c];
        }
        __syncthreads();
        #pragma unroll
        for (int kk = 0; kk < 16; kk++) {
            float a[4], bb[4];
            #pragma unroll
            for (int i = 0; i < 4; i++) a[i] = As[ty * 4 + i][kk];
            #pragma unroll
            for (int j = 0; j < 4; j++) bb[j] = Bs[kk][tx * 4 + j];
            #pragma unroll
            for (int i = 0; i < 4; i++)
                #pragma unroll
                for (int j = 0; j < 4; j++) acc[i][j] += a[i] * bb[j];
        }
        __syncthreads();
    }
    #pragma unroll
    for (int i = 0; i < 4; i++) {
        int m = m0 + ty * 4 + i;
        #pragma unroll
        for (int j = 0; j < 4; j++) {
            int col = n0 + tx * 4 + j;
            out[(size_t)m * DIMM + col] = acc[i][j] + bo[col];
        }
    }
}

// ---------------------------------------------------------------------------
extern "C" void kernel_launch(void* const* d_in, const int* in_sizes, int n_in,
                              void* d_out, int out_size) {
    const float* x        = (const float*)d_in[0];
    const float* mem_kv   = (const float*)d_in[1];
    const float* mem_mask = (const float*)d_in[2];
    const float* Wq       = (const float*)d_in[3];
    const float* Wkv      = (const float*)d_in[4];
    const float* Wo       = (const float*)d_in[5];
    const float* bo       = (const float*)d_in[6];
    const float* null_k   = (const float*)d_in[7];
    const float* null_v   = (const float*)d_in[8];
    const float* gate     = (const float*)d_in[9];
    float* out = (float*)d_out;

    // K1: QKV projection
    qkv_kernel<<<dim3(10, 64), 256>>>(x, Wq, Wkv);

    // K2: local causal flash attention (needs >48KB dynamic smem)
    size_t smemB = 4 * 64 * 65 * sizeof(float);
    cudaFuncSetAttribute(local_attn_kernel,
                         cudaFuncAttributeMaxDynamicSharedMemorySize, (int)smemB);
    local_attn_kernel<<<dim3(NN / 64, BB * HH), 256, smemB>>>();

    // K3: memory attention + gate combine (one warp per (b,h,i))
    mem_attn_kernel<<<(BB * HH * NN * 32) / 256, 256>>>(mem_kv, mem_mask,
                                                        null_k, null_v, gate);

    // K4: output projection + bias
    out_proj_kernel<<<dim3(DIMM / 64, M_TOT / 64), 256>>>(Wo, bo, out);
}

// round 3
// speedup vs baseline: 1.5860x; 1.5860x over previous
#include <cuda_runtime.h>
#include <math.h>
#include <stdint.h>

#define BB 2
#define NN 2048
#define DIMM 512
#define HH 8
#define DHH 64
#define KNN 32
#define SCALE 0.125f
#define M_TOT (BB*NN)   // 4096

// Scratch (allocation-free rule: __device__ globals)
__device__ float g_q[BB*HH*NN*DHH];      // (b,h,n,d)
__device__ float g_k[BB*NN*DHH];         // (b,n,d)
__device__ float g_v[BB*NN*DHH];
__device__ float g_local[BB*HH*NN*DHH];  // (b,h,n,d)
__device__ float g_comb[BB*NN*HH*DHH];   // (b,n,h*64+d)

// ---------------------------------------------------------------------------
// tf32 helpers
// ---------------------------------------------------------------------------
__device__ __forceinline__ unsigned f2tf(float x) {
    unsigned r;
    asm("cvt.rna.tf32.f32 %0, %1;" : "=r"(r) : "f"(x));
    return r;
}
__device__ __forceinline__ float tfval(float x) {
    return __uint_as_float(f2tf(x));
}
__device__ __forceinline__ void mma_tf32(float c[4],
                                         unsigned a0, unsigned a1, unsigned a2, unsigned a3,
                                         unsigned b0, unsigned b1) {
    asm volatile(
        "mma.sync.aligned.m16n8k8.row.col.f32.tf32.tf32.f32 "
        "{%0,%1,%2,%3},{%4,%5,%6,%7},{%8,%9},{%0,%1,%2,%3};"
        : "+f"(c[0]), "+f"(c[1]), "+f"(c[2]), "+f"(c[3])
        : "r"(a0), "r"(a1), "r"(a2), "r"(a3), "r"(b0), "r"(b1));
}
// split x into hi (tf32) + lo (tf32 of residual)
__device__ __forceinline__ void tf_split(float x, float& hi, float& lo) {
    hi = tfval(x);
    lo = tfval(x - hi);
}

// ---------------------------------------------------------------------------
// Split-tf32 GEMM (near-fp32 accuracy): BM=128, BN=64, BK=32, 256 thr, 8 warps
// smem layout (floats): Ah[128*36] Al[128*36] Bh[32*72] Bl[32*72] = 13824
// ---------------------------------------------------------------------------
#define G_LDA 36
#define G_LDB 72
#define GEMM_SMEM_FLOATS (2*128*G_LDA + 2*32*G_LDB)

// K1: x[4096x512] @ [Wq | Wkv] -> scatter into g_q / g_k / g_v
extern "C" __global__ __launch_bounds__(256)
void qkv_kernel(const float* __restrict__ x,
                const float* __restrict__ Wq,
                const float* __restrict__ Wkv) {
    extern __shared__ float sm[];
    float* Ah = sm;
    float* Al = Ah + 128 * G_LDA;
    float* Bh = Al + 128 * G_LDA;
    float* Bl = Bh + 32 * G_LDB;

    int tid = threadIdx.x;
    int lane = tid & 31, wid = tid >> 5;
    int warpM = wid >> 1, warpN = wid & 1;
    int lr = lane >> 2, lc = lane & 3;
    int n0 = blockIdx.x * 64;
    int m0 = blockIdx.y * 128;

    float acc[2][4][4];
    #pragma unroll
    for (int mi = 0; mi < 2; mi++)
        #pragma unroll
        for (int ni = 0; ni < 4; ni++)
            #pragma unroll
            for (int t = 0; t < 4; t++) acc[mi][ni][t] = 0.f;

    for (int k0 = 0; k0 < DIMM; k0 += 32) {
        __syncthreads();
        // load A tile 128x32
        #pragma unroll
        for (int p = 0; p < 4; p++) {
            int r = (tid >> 3) + p * 32;
            int c = (tid & 7) * 4;
            float4 v = *(const float4*)(x + (size_t)(m0 + r) * DIMM + k0 + c);
            float h0, l0, h1, l1, h2, l2, h3, l3;
            tf_split(v.x, h0, l0); tf_split(v.y, h1, l1);
            tf_split(v.z, h2, l2); tf_split(v.w, h3, l3);
            float* ph = Ah + r * G_LDA + c;
            float* pl = Al + r * G_LDA + c;
            ph[0] = h0; ph[1] = h1; ph[2] = h2; ph[3] = h3;
            pl[0] = l0; pl[1] = l1; pl[2] = l2; pl[3] = l3;
        }
        // load B tile 32x64 (cols may come from Wq or Wkv)
        #pragma unroll
        for (int p = 0; p < 2; p++) {
            int r = (tid >> 4) + p * 16;
            int c = (tid & 15) * 4;
            int j = n0 + c;
            float4 v;
            if (j < 512) v = *(const float4*)(Wq + (size_t)(k0 + r) * 512 + j);
            else         v = *(const float4*)(Wkv + (size_t)(k0 + r) * 128 + (j - 512));
            float h0, l0, h1, l1, h2, l2, h3, l3;
            tf_split(v.x, h0, l0); tf_split(v.y, h1, l1);
            tf_split(v.z, h2, l2); tf_split(v.w, h3, l3);
            float* ph = Bh + r * G_LDB + c;
            float* pl = Bl + r * G_LDB + c;
            ph[0] = h0; ph[1] = h1; ph[2] = h2; ph[3] = h3;
            pl[0] = l0; pl[1] = l1; pl[2] = l2; pl[3] = l3;
        }
        __syncthreads();

        #pragma unroll
        for (int kk = 0; kk < 4; kk++) {
            int kc = kk * 8 + lc;
            unsigned ah[2][4], al[2][4];
            #pragma unroll
            for (int mi = 0; mi < 2; mi++) {
                int r = warpM * 32 + mi * 16 + lr;
                ah[mi][0] = __float_as_uint(Ah[r * G_LDA + kc]);
                ah[mi][1] = __float_as_uint(Ah[(r + 8) * G_LDA + kc]);
                ah[mi][2] = __float_as_uint(Ah[r * G_LDA + kc + 4]);
                ah[mi][3] = __float_as_uint(Ah[(r + 8) * G_LDA + kc + 4]);
                al[mi][0] = __float_as_uint(Al[r * G_LDA + kc]);
                al[mi][1] = __float_as_uint(Al[(r + 8) * G_LDA + kc]);
                al[mi][2] = __float_as_uint(Al[r * G_LDA + kc + 4]);
                al[mi][3] = __float_as_uint(Al[(r + 8) * G_LDA + kc + 4]);
            }
            unsigned bh[4][2], bl[4][2];
            #pragma unroll
            for (int ni = 0; ni < 4; ni++) {
                int n = warpN * 32 + ni * 8 + lr;
                bh[ni][0] = __float_as_uint(Bh[kc * G_LDB + n]);
                bh[ni][1] = __float_as_uint(Bh[(kc + 4) * G_LDB + n]);
                bl[ni][0] = __float_as_uint(Bl[kc * G_LDB + n]);
                bl[ni][1] = __float_as_uint(Bl[(kc + 4) * G_LDB + n]);
            }
            #pragma unroll
            for (int mi = 0; mi < 2; mi++)
                #pragma unroll
                for (int ni = 0; ni < 4; ni++) {
                    mma_tf32(acc[mi][ni], ah[mi][0], ah[mi][1], ah[mi][2], ah[mi][3],
                             bh[ni][0], bh[ni][1]);
                    mma_tf32(acc[mi][ni], ah[mi][0], ah[mi][1], ah[mi][2], ah[mi][3],
                             bl[ni][0], bl[ni][1]);
                    mma_tf32(acc[mi][ni], al[mi][0], al[mi][1], al[mi][2], al[mi][3],
                             bh[ni][0], bh[ni][1]);
                }
        }
    }

    // epilogue: scatter
    #pragma unroll
    for (int mi = 0; mi < 2; mi++)
        #pragma unroll
        for (int ni = 0; ni < 4; ni++)
            #pragma unroll
            for (int t = 0; t < 4; t++) {
                int m = m0 + warpM * 32 + mi * 16 + lr + ((t >= 2) ? 8 : 0);
                int col = n0 + warpN * 32 + ni * 8 + lc * 2 + (t & 1);
                float val = acc[mi][ni][t];
                int b = m >> 11, n = m & 2047;
                if (col < 512) {
                    int h = col >> 6, d = col & 63;
                    g_q[(((size_t)(b * HH + h) * NN) + n) * DHH + d] = val;
                } else if (col < 576) {
                    g_k[(size_t)m * DHH + (col - 512)] = val;
                } else {
                    g_v[(size_t)m * DHH + (col - 576)] = val;
                }
            }
}

// K4: g_comb[4096x512] @ Wo[512x512] + bo
extern "C" __global__ __launch_bounds__(256)
void out_proj_kernel(const float* __restrict__ Wo,
                     const float* __restrict__ bo,
                     float* __restrict__ out) {
    extern __shared__ float sm[];
    float* Ah = sm;
    float* Al = Ah + 128 * G_LDA;
    float* Bh = Al + 128 * G_LDA;
    float* Bl = Bh + 32 * G_LDB;

    int tid = threadIdx.x;
    int lane = tid & 31, wid = tid >> 5;
    int warpM = wid >> 1, warpN = wid & 1;
    int lr = lane >> 2, lc = lane & 3;
    int n0 = blockIdx.x * 64;
    int m0 = blockIdx.y * 128;

    float acc[2][4][4];
    #pragma unroll
    for (int mi = 0; mi < 2; mi++)
        #pragma unroll
        for (int ni = 0; ni < 4; ni++)
            #pragma unroll
            for (int t = 0; t < 4; t++) acc[mi][ni][t] = 0.f;

    for (int k0 = 0; k0 < DIMM; k0 += 32) {
        __syncthreads();
        #pragma unroll
        for (int p = 0; p < 4; p++) {
            int r = (tid >> 3) + p * 32;
            int c = (tid & 7) * 4;
            float4 v = *(const float4*)(g_comb + (size_t)(m0 + r) * DIMM + k0 + c);
            float h0, l0, h1, l1, h2, l2, h3, l3;
            tf_split(v.x, h0, l0); tf_split(v.y, h1, l1);
            tf_split(v.z, h2, l2); tf_split(v.w, h3, l3);
            float* ph = Ah + r * G_LDA + c;
            float* pl = Al + r * G_LDA + c;
            ph[0] = h0; ph[1] = h1; ph[2] = h2; ph[3] = h3;
            pl[0] = l0; pl[1] = l1; pl[2] = l2; pl[3] = l3;
        }
        #pragma unroll
        for (int p = 0; p < 2; p++) {
            int r = (tid >> 4) + p * 16;
            int c = (tid & 15) * 4;
            float4 v = *(const float4*)(Wo + (size_t)(k0 + r) * DIMM + n0 + c);
            float h0, l0, h1, l1, h2, l2, h3, l3;
            tf_split(v.x, h0, l0); tf_split(v.y, h1, l1);
            tf_split(v.z, h2, l2); tf_split(v.w, h3, l3);
            float* ph = Bh + r * G_LDB + c;
            float* pl = Bl + r * G_LDB + c;
            ph[0] = h0; ph[1] = h1; ph[2] = h2; ph[3] = h3;
            pl[0] = l0; pl[1] = l1; pl[2] = l2; pl[3] = l3;
        }
        __syncthreads();

        #pragma unroll
        for (int kk = 0; kk < 4; kk++) {
            int kc = kk * 8 + lc;
            unsigned ah[2][4], al[2][4];
            #pragma unroll
            for (int mi = 0; mi < 2; mi++) {
                int r = warpM * 32 + mi * 16 + lr;
                ah[mi][0] = __float_as_uint(Ah[r * G_LDA + kc]);
                ah[mi][1] = __float_as_uint(Ah[(r + 8) * G_LDA + kc]);
                ah[mi][2] = __float_as_uint(Ah[r * G_LDA + kc + 4]);
                ah[mi][3] = __float_as_uint(Ah[(r + 8) * G_LDA + kc + 4]);
                al[mi][0] = __float_as_uint(Al[r * G_LDA + kc]);
                al[mi][1] = __float_as_uint(Al[(r + 8) * G_LDA + kc]);
                al[mi][2] = __float_as_uint(Al[r * G_LDA + kc + 4]);
                al[mi][3] = __float_as_uint(Al[(r + 8) * G_LDA + kc + 4]);
            }
            unsigned bh[4][2], bl[4][2];
            #pragma unroll
            for (int ni = 0; ni < 4; ni++) {
                int n = warpN * 32 + ni * 8 + lr;
                bh[ni][0] = __float_as_uint(Bh[kc * G_LDB + n]);
                bh[ni][1] = __float_as_uint(Bh[(kc + 4) * G_LDB + n]);
                bl[ni][0] = __float_as_uint(Bl[kc * G_LDB + n]);
                bl[ni][1] = __float_as_uint(Bl[(kc + 4) * G_LDB + n]);
            }
            #pragma unroll
            for (int mi = 0; mi < 2; mi++)
                #pragma unroll
                for (int ni = 0; ni < 4; ni++) {
                    mma_tf32(acc[mi][ni], ah[mi][0], ah[mi][1], ah[mi][2], ah[mi][3],
                             bh[ni][0], bh[ni][1]);
                    mma_tf32(acc[mi][ni], ah[mi][0], ah[mi][1], ah[mi][2], ah[mi][3],
                             bl[ni][0], bl[ni][1]);
                    mma_tf32(acc[mi][ni], al[mi][0], al[mi][1], al[mi][2], al[mi][3],
                             bh[ni][0], bh[ni][1]);
                }
        }
    }

    #pragma unroll
    for (int mi = 0; mi < 2; mi++)
        #pragma unroll
        for (int ni = 0; ni < 4; ni++)
            #pragma unroll
            for (int t = 0; t < 4; t++) {
                int m = m0 + warpM * 32 + mi * 16 + lr + ((t >= 2) ? 8 : 0);
                int col = n0 + warpN * 32 + ni * 8 + lc * 2 + (t & 1);
                out[(size_t)m * DIMM + col] = acc[mi][ni][t] + bo[col];
            }
}

// ---------------------------------------------------------------------------
// K2: local causal flash attention with tf32 mma.
// Block = 64 query rows of one (b,h); 4 warps (each owns 16 rows, all 64 cols).
// QK^T uses split tf32 (3 mma); PV single tf32.
// smem (floats): Qh Ql Kh Kl [64*72 each], Vs[64*72], Ps[64*72] = 27648
// ---------------------------------------------------------------------------
#define A_LD 72
#define ATTN_SMEM_FLOATS (6*64*A_LD)

extern "C" __global__ __launch_bounds__(128)
void local_attn_kernel() {
    extern __shared__ float sm[];
    float* Qh = sm;
    float* Ql = Qh + 64 * A_LD;
    float* Kh = Ql + 64 * A_LD;
    float* Kl = Kh + 64 * A_LD;
    float* Vs = Kl + 64 * A_LD;
    float* Ps = Vs + 64 * A_LD;

    int tid = threadIdx.x;
    int lane = tid & 31, warp = tid >> 5;
    int lr = lane >> 2, lc = lane & 3;
    int bh = blockIdx.y;
    int b = bh / HH;
    int i0 = blockIdx.x * 64;

    const float* qbase = g_q + (size_t)bh * NN * DHH;
    const float* kbase = g_k + (size_t)b * NN * DHH;
    const float* vbase = g_v + (size_t)b * NN * DHH;

    // load Q tile (64x64) with split
    #pragma unroll
    for (int p = 0; p < 8; p++) {
        int r = (tid >> 4) + p * 8;
        int c = (tid & 15) * 4;
        float4 v = *(const float4*)(qbase + (size_t)(i0 + r) * DHH + c);
        float h0, l0, h1, l1, h2, l2, h3, l3;
        tf_split(v.x, h0, l0); tf_split(v.y, h1, l1);
        tf_split(v.z, h2, l2); tf_split(v.w, h3, l3);
        float* ph = Qh + r * A_LD + c;
        float* pl = Ql + r * A_LD + c;
        ph[0] = h0; ph[1] = h1; ph[2] = h2; ph[3] = h3;
        pl[0] = l0; pl[1] = l1; pl[2] = l2; pl[3] = l3;
    }

    float out[8][4];
    #pragma unroll
    for (int ni = 0; ni < 8; ni++)
        #pragma unroll
        for (int t = 0; t < 4; t++) out[ni][t] = 0.f;
    float m0_ = -1e30f, m1_ = -1e30f, l0_ = 0.f, l1_ = 0.f;

    int gi0 = i0 + warp * 16 + lr;
    int gi1 = gi0 + 8;
    int prow = warp * 16 + lr;

    for (int j0 = 0; j0 <= i0; j0 += 64) {
        __syncthreads();
        // load K (split) and V (single) tiles
        #pragma unroll
        for (int p = 0; p < 8; p++) {
            int r = (tid >> 4) + p * 8;
            int c = (tid & 15) * 4;
            float4 kv = *(const float4*)(kbase + (size_t)(j0 + r) * DHH + c);
            float h0, l0, h1, l1, h2, l2, h3, l3;
            tf_split(kv.x, h0, l0); tf_split(kv.y, h1, l1);
            tf_split(kv.z, h2, l2); tf_split(kv.w, h3, l3);
            float* ph = Kh + r * A_LD + c;
            float* pl = Kl + r * A_LD + c;
            ph[0] = h0; ph[1] = h1; ph[2] = h2; ph[3] = h3;
            pl[0] = l0; pl[1] = l1; pl[2] = l2; pl[3] = l3;
            float4 vv = *(const float4*)(vbase + (size_t)(j0 + r) * DHH + c);
            float* pv = Vs + r * A_LD + c;
            pv[0] = tfval(vv.x); pv[1] = tfval(vv.y);
            pv[2] = tfval(vv.z); pv[3] = tfval(vv.w);
        }
        __syncthreads();

        // S = Q K^T (split tf32)
        float s[8][4];
        #pragma unroll
        for (int ni = 0; ni < 8; ni++)
            #pragma unroll
            for (int t = 0; t < 4; t++) s[ni][t] = 0.f;

        #pragma unroll
        for (int kk = 0; kk < 8; kk++) {
            int kc = kk * 8 + lc;
            unsigned ah0 = __float_as_uint(Qh[prow * A_LD + kc]);
            unsigned ah1 = __float_as_uint(Qh[(prow + 8) * A_LD + kc]);
            unsigned ah2 = __float_as_uint(Qh[prow * A_LD + kc + 4]);
            unsigned ah3 = __float_as_uint(Qh[(prow + 8) * A_LD + kc + 4]);
            unsigned al0 = __float_as_uint(Ql[prow * A_LD + kc]);
            unsigned al1 = __float_as_uint(Ql[(prow + 8) * A_LD + kc]);
            unsigned al2 = __float_as_uint(Ql[prow * A_LD + kc + 4]);
            unsigned al3 = __float_as_uint(Ql[(prow + 8) * A_LD + kc + 4]);
            #pragma unroll
            for (int ni = 0; ni < 8; ni++) {
                int n = ni * 8 + lr;
                unsigned bh0 = __float_as_uint(Kh[n * A_LD + kc]);
                unsigned bh1 = __float_as_uint(Kh[n * A_LD + kc + 4]);
                unsigned bl0 = __float_as_uint(Kl[n * A_LD + kc]);
                unsigned bl1 = __float_as_uint(Kl[n * A_LD + kc + 4]);
                mma_tf32(s[ni], ah0, ah1, ah2, ah3, bh0, bh1);
                mma_tf32(s[ni], ah0, ah1, ah2, ah3, bl0, bl1);
                mma_tf32(s[ni], al0, al1, al2, al3, bh0, bh1);
            }
        }

        // scale + causal mask + row max
        bool diag = (j0 == i0);
        float mx0 = -1e30f, mx1 = -1e30f;
        #pragma unroll
        for (int ni = 0; ni < 8; ni++) {
            int gj = j0 + ni * 8 + lc * 2;
            s[ni][0] *= SCALE; s[ni][1] *= SCALE;
            s[ni][2] *= SCALE; s[ni][3] *= SCALE;
            if (diag) {
                if (gj > gi0)     s[ni][0] = -1e30f;
                if (gj + 1 > gi0) s[ni][1] = -1e30f;
                if (gj > gi1)     s[ni][2] = -1e30f;
                if (gj + 1 > gi1) s[ni][3] = -1e30f;
            }
            mx0 = fmaxf(mx0, fmaxf(s[ni][0], s[ni][1]));
            mx1 = fmaxf(mx1, fmaxf(s[ni][2], s[ni][3]));
        }
        mx0 = fmaxf(mx0, __shfl_xor_sync(0xffffffffu, mx0, 1));
        mx0 = fmaxf(mx0, __shfl_xor_sync(0xffffffffu, mx0, 2));
        mx1 = fmaxf(mx1, __shfl_xor_sync(0xffffffffu, mx1, 1));
        mx1 = fmaxf(mx1, __shfl_xor_sync(0xffffffffu, mx1, 2));

        float mn0 = fmaxf(m0_, mx0), mn1 = fmaxf(m1_, mx1);
        float corr0 = __expf(m0_ - mn0), corr1 = __expf(m1_ - mn1);
        float sum0 = 0.f, sum1 = 0.f;
        #pragma unroll
        for (int ni = 0; ni < 8; ni++) {
            float p0 = __expf(s[ni][0] - mn0);
            float p1 = __expf(s[ni][1] - mn0);
            float p2 = __expf(s[ni][2] - mn1);
            float p3 = __expf(s[ni][3] - mn1);
            sum0 += p0 + p1; sum1 += p2 + p3;
            int c = ni * 8 + lc * 2;
            Ps[prow * A_LD + c]       = tfval(p0);
            Ps[prow * A_LD + c + 1]   = tfval(p1);
            Ps[(prow + 8) * A_LD + c]     = tfval(p2);
            Ps[(prow + 8) * A_LD + c + 1] = tfval(p3);
        }
        sum0 += __shfl_xor_sync(0xffffffffu, sum0, 1);
        sum0 += __shfl_xor_sync(0xffffffffu, sum0, 2);
        sum1 += __shfl_xor_sync(0xffffffffu, sum1, 1);
        sum1 += __shfl_xor_sync(0xffffffffu, sum1, 2);
        l0_ = l0_ * corr0 + sum0;
        l1_ = l1_ * corr1 + sum1;
        m0_ = mn0; m1_ = mn1;

        #pragma unroll
        for (int ni = 0; ni < 8; ni++) {
            out[ni][0] *= corr0; out[ni][1] *= corr0;
            out[ni][2] *= corr1; out[ni][3] *= corr1;
        }
        __syncwarp();

        // out += P @ V  (single tf32)
        #pragma unroll
        for (int kk = 0; kk < 8; kk++) {
            int kc = kk * 8 + lc;
            unsigned pa0 = __float_as_uint(Ps[prow * A_LD + kc]);
            unsigned pa1 = __float_as_uint(Ps[(prow + 8) * A_LD + kc]);
            unsigned pa2 = __float_as_uint(Ps[prow * A_LD + kc + 4]);
            unsigned pa3 = __float_as_uint(Ps[(prow + 8) * A_LD + kc + 4]);
            #pragma unroll
            for (int ni = 0; ni < 8; ni++) {
                int n = ni * 8 + lr;
                unsigned vb0 = __float_as_uint(Vs[kc * A_LD + n]);
                unsigned vb1 = __float_as_uint(Vs[(kc + 4) * A_LD + n]);
                mma_tf32(out[ni], pa0, pa1, pa2, pa3, vb0, vb1);
            }
        }
    }

    float inv0 = 1.f / l0_, inv1 = 1.f / l1_;
    float* lbase = g_local + (size_t)bh * NN * DHH;
    #pragma unroll
    for (int ni = 0; ni < 8; ni++) {
        int c = ni * 8 + lc * 2;
        int r0 = i0 + prow, r1 = r0 + 8;
        lbase[(size_t)r0 * DHH + c]     = out[ni][0] * inv0;
        lbase[(size_t)r0 * DHH + c + 1] = out[ni][1] * inv0;
        lbase[(size_t)r1 * DHH + c]     = out[ni][2] * inv1;
        lbase[(size_t)r1 * DHH + c + 1] = out[ni][3] * inv1;
    }
}

// ---------------------------------------------------------------------------
// K3: memory attention + gate combine.  One warp per (b,h,i).  (unchanged)
// ---------------------------------------------------------------------------
__global__ void mem_attn_kernel(const float* __restrict__ mem_kv,
                                const float* __restrict__ mem_mask,
                                const float* __restrict__ null_k,
                                const float* __restrict__ null_v,
                                const float* __restrict__ gate) {
    int warp = (blockIdx.x * blockDim.x + threadIdx.x) >> 5;
    int lane = threadIdx.x & 31;
    if (warp >= BB * HH * NN) return;
    int i = warp % NN;
    int bh = warp / NN;
    int h = bh % HH;
    int b = bh / HH;

    float2 q2 = *(const float2*)(g_q + (size_t)warp * DHH + lane * 2);
    const float* kvbase = mem_kv + (size_t)warp * KNN * 2 * DHH;
    const float* maskbase = mem_mask + (size_t)warp * KNN;

    float m, l;
    float2 acc;
    {
        float2 k2 = *(const float2*)(null_k + lane * 2);
        float part = q2.x * k2.x + q2.y * k2.y;
        #pragma unroll
        for (int o = 16; o >= 1; o >>= 1)
            part += __shfl_xor_sync(0xffffffffu, part, o);
        m = part * SCALE;
        l = 1.f;
        acc = *(const float2*)(null_v + lane * 2);
    }
    for (int j = 0; j < KNN; j++) {
        const float* kp = kvbase + (size_t)j * 2 * DHH;
        float2 k2 = *(const float2*)(kp + lane * 2);
        float2 v2 = *(const float2*)(kp + DHH + lane * 2);
        float part = q2.x * k2.x + q2.y * k2.y;
        #pragma unroll
        for (int o = 16; o >= 1; o >>= 1)
            part += __shfl_xor_sync(0xffffffffu, part, o);
        bool valid = (maskbase[j] != 0.0f);
        if (!valid) continue;
        float s = part * SCALE;
        float m_new = fmaxf(m, s);
        float corr = __expf(m - m_new);
        float w = __expf(s - m_new);
        l = l * corr + w;
        acc.x = acc.x * corr + w * v2.x;
        acc.y = acc.y * corr + w * v2.y;
        m = m_new;
    }
    float inv = 1.f / l;
    float g = 1.f / (1.f + __expf(-gate[h]));
    float2 lv = *(const float2*)(g_local + (size_t)warp * DHH + lane * 2);
    float2 oc;
    oc.x = lv.x * g + acc.x * inv * (1.f - g);
    oc.y = lv.y * g + acc.y * inv * (1.f - g);
    float* cp = g_comb + ((size_t)(b * NN + i)) * (HH * DHH) + h * DHH;
    *(float2*)(cp + lane * 2) = oc;
}

// ---------------------------------------------------------------------------
extern "C" void kernel_launch(void* const* d_in, const int* in_sizes, int n_in,
                              void* d_out, int out_size) {
    const float* x        = (const float*)d_in[0];
    const float* mem_kv   = (const float*)d_in[1];
    const float* mem_mask = (const float*)d_in[2];
    const float* Wq       = (const float*)d_in[3];
    const float* Wkv      = (const float*)d_in[4];
    const float* Wo       = (const float*)d_in[5];
    const float* bo       = (const float*)d_in[6];
    const float* null_k   = (const float*)d_in[7];
    const float* null_v   = (const float*)d_in[8];
    const float* gate     = (const float*)d_in[9];
    float* out = (float*)d_out;

    size_t gemm_smem = GEMM_SMEM_FLOATS * sizeof(float);
    size_t attn_smem = ATTN_SMEM_FLOATS * sizeof(float);

    cudaFuncSetAttribute(qkv_kernel,
                         cudaFuncAttributeMaxDynamicSharedMemorySize, (int)gemm_smem);
    cudaFuncSetAttribute(out_proj_kernel,
                         cudaFuncAttributeMaxDynamicSharedMemorySize, (int)gemm_smem);
    cudaFuncSetAttribute(local_attn_kernel,
                         cudaFuncAttributeMaxDynamicSharedMemorySize, (int)attn_smem);

    // K1: QKV projection (split tf32 tensor cores)  [4096/128=32 M-tiles]
    qkv_kernel<<<dim3(10, 32), 256, gemm_smem>>>(x, Wq, Wkv);

    // K2: local causal flash attention (tf32 mma)
    local_attn_kernel<<<dim3(NN / 64, BB * HH), 128, attn_smem>>>();

    // K3: memory attention + gate combine
    mem_attn_kernel<<<(BB * HH * NN * 32) / 256, 256>>>(mem_kv, mem_mask,
                                                        null_k, null_v, gate);

    // K4: output projection + bias (split tf32, BM=128 -> grid y = 4096/128 = 32)
    out_proj_kernel<<<dim3(DIMM / 64, M_TOT / 128), 256, gemm_smem>>>(Wo, bo, out);
}

// round 15
// speedup vs baseline: 1.7349x; 1.0939x over previous
#include <cuda_runtime.h>
#include <math.h>
#include <stdint.h>

#define BB 2
#define NN 2048
#define DIMM 512
#define HH 8
#define DHH 64
#define KNN 32
#define SCALE 0.125f
#define M_TOT (BB*NN)   // 4096

// Scratch (allocation-free rule: __device__ globals)
__device__ float g_q[BB*HH*NN*DHH];      // (b,h,n,d)
__device__ float g_k[BB*NN*DHH];         // (b,n,d)
__device__ float g_v[BB*NN*DHH];
__device__ float g_local[BB*HH*NN*DHH];  // (b,h,n,d)  normalized local attn
__device__ float g_mem[BB*HH*NN*DHH];    // (b,h,n,d)  normalized mem attn

// ---------------------------------------------------------------------------
// tf32 helpers
// ---------------------------------------------------------------------------
__device__ __forceinline__ unsigned f2tf(float x) {
    unsigned r;
    asm("cvt.rna.tf32.f32 %0, %1;" : "=r"(r) : "f"(x));
    return r;
}
__device__ __forceinline__ float tfval(float x) {
    return __uint_as_float(f2tf(x));
}
__device__ __forceinline__ void mma_tf32(float c[4],
                                         unsigned a0, unsigned a1, unsigned a2, unsigned a3,
                                         unsigned b0, unsigned b1) {
    asm volatile(
        "mma.sync.aligned.m16n8k8.row.col.f32.tf32.tf32.f32 "
        "{%0,%1,%2,%3},{%4,%5,%6,%7},{%8,%9},{%0,%1,%2,%3};"
        : "+f"(c[0]), "+f"(c[1]), "+f"(c[2]), "+f"(c[3])
        : "r"(a0), "r"(a1), "r"(a2), "r"(a3), "r"(b0), "r"(b1));
}
__device__ __forceinline__ void tf_split(float x, float& hi, float& lo) {
    hi = tfval(x);
    lo = tfval(x - hi);
}
// split to raw-bit tf32 regs
__device__ __forceinline__ void tf_split_u(float x, unsigned& hi, unsigned& lo) {
    float h = tfval(x);
    hi = __float_as_uint(h);
    lo = f2tf(x - h);
}

// ---------------------------------------------------------------------------
// Split-tf32 GEMM: BM=64, BN=64, BK=32, 256 thr, 8 warps (2 warpM x 4 warpN).
// smem static 36KB: Ah/Al[64*36], Bh/Bl[32*72].
// ---------------------------------------------------------------------------
#define G_LDA 36
#define G_LDB 72

// K1: x[4096x512] @ [Wq | Wkv] -> scatter into g_q / g_k / g_v
extern "C" __global__ __launch_bounds__(256)
void qkv_kernel(const float* __restrict__ x,
                const float* __restrict__ Wq,
                const float* __restrict__ Wkv) {
    __shared__ float Ah[64 * G_LDA], Al[64 * G_LDA];
    __shared__ float Bh[32 * G_LDB], Bl[32 * G_LDB];

    int tid = threadIdx.x;
    int lane = tid & 31, wid = tid >> 5;
    int warpM = wid >> 2, warpN = wid & 3;
    int lr = lane >> 2, lc = lane & 3;
    int n0 = blockIdx.x * 64;
    int m0 = blockIdx.y * 64;

    float acc[2][2][4];
    #pragma unroll
    for (int mi = 0; mi < 2; mi++)
        #pragma unroll
        for (int ni = 0; ni < 2; ni++)
            #pragma unroll
            for (int t = 0; t < 4; t++) acc[mi][ni][t] = 0.f;

    for (int k0 = 0; k0 < DIMM; k0 += 32) {
        __syncthreads();
        // A tile 64x32
        #pragma unroll
        for (int p = 0; p < 2; p++) {
            int r = (tid >> 3) + p * 32;
            int c = (tid & 7) * 4;
            float4 v = *(const float4*)(x + (size_t)(m0 + r) * DIMM + k0 + c);
            float h0, l0, h1, l1, h2, l2, h3, l3;
            tf_split(v.x, h0, l0); tf_split(v.y, h1, l1);
            tf_split(v.z, h2, l2); tf_split(v.w, h3, l3);
            float* ph = Ah + r * G_LDA + c;
            float* pl = Al + r * G_LDA + c;
            ph[0] = h0; ph[1] = h1; ph[2] = h2; ph[3] = h3;
            pl[0] = l0; pl[1] = l1; pl[2] = l2; pl[3] = l3;
        }
        // B tile 32x64 (cols from Wq or Wkv)
        #pragma unroll
        for (int p = 0; p < 2; p++) {
            int r = (tid >> 4) + p * 16;
            int c = (tid & 15) * 4;
            int j = n0 + c;
            float4 v;
            if (j < 512) v = *(const float4*)(Wq + (size_t)(k0 + r) * 512 + j);
            else         v = *(const float4*)(Wkv + (size_t)(k0 + r) * 128 + (j - 512));
            float h0, l0, h1, l1, h2, l2, h3, l3;
            tf_split(v.x, h0, l0); tf_split(v.y, h1, l1);
            tf_split(v.z, h2, l2); tf_split(v.w, h3, l3);
            float* ph = Bh + r * G_LDB + c;
            float* pl = Bl + r * G_LDB + c;
            ph[0] = h0; ph[1] = h1; ph[2] = h2; ph[3] = h3;
            pl[0] = l0; pl[1] = l1; pl[2] = l2; pl[3] = l3;
        }
        __syncthreads();

        #pragma unroll
        for (int kk = 0; kk < 4; kk++) {
            int kc = kk * 8 + lc;
            unsigned ah[2][4], al[2][4];
            #pragma unroll
            for (int mi = 0; mi < 2; mi++) {
                int r = warpM * 32 + mi * 16 + lr;
                ah[mi][0] = __float_as_uint(Ah[r * G_LDA + kc]);
                ah[mi][1] = __float_as_uint(Ah[(r + 8) * G_LDA + kc]);
                ah[mi][2] = __float_as_uint(Ah[r * G_LDA + kc + 4]);
                ah[mi][3] = __float_as_uint(Ah[(r + 8) * G_LDA + kc + 4]);
                al[mi][0] = __float_as_uint(Al[r * G_LDA + kc]);
                al[mi][1] = __float_as_uint(Al[(r + 8) * G_LDA + kc]);
                al[mi][2] = __float_as_uint(Al[r * G_LDA + kc + 4]);
                al[mi][3] = __float_as_uint(Al[(r + 8) * G_LDA + kc + 4]);
            }
            unsigned bh[2][2], bl[2][2];
            #pragma unroll
            for (int ni = 0; ni < 2; ni++) {
                int n = warpN * 16 + ni * 8 + lr;
                bh[ni][0] = __float_as_uint(Bh[kc * G_LDB + n]);
                bh[ni][1] = __float_as_uint(Bh[(kc + 4) * G_LDB + n]);
                bl[ni][0] = __float_as_uint(Bl[kc * G_LDB + n]);
                bl[ni][1] = __float_as_uint(Bl[(kc + 4) * G_LDB + n]);
            }
            #pragma unroll
            for (int mi = 0; mi < 2; mi++)
                #pragma unroll
                for (int ni = 0; ni < 2; ni++) {
                    mma_tf32(acc[mi][ni], ah[mi][0], ah[mi][1], ah[mi][2], ah[mi][3],
                             bh[ni][0], bh[ni][1]);
                    mma_tf32(acc[mi][ni], ah[mi][0], ah[mi][1], ah[mi][2], ah[mi][3],
                             bl[ni][0], bl[ni][1]);
                    mma_tf32(acc[mi][ni], al[mi][0], al[mi][1], al[mi][2], al[mi][3],
                             bh[ni][0], bh[ni][1]);
                }
        }
    }

    #pragma unroll
    for (int mi = 0; mi < 2; mi++)
        #pragma unroll
        for (int ni = 0; ni < 2; ni++)
            #pragma unroll
            for (int t = 0; t < 4; t++) {
                int m = m0 + warpM * 32 + mi * 16 + lr + ((t >= 2) ? 8 : 0);
                int col = n0 + warpN * 16 + ni * 8 + lc * 2 + (t & 1);
                float val = acc[mi][ni][t];
                int b = m >> 11, n = m & 2047;
                if (col < 512) {
                    int h = col >> 6, d = col & 63;
                    g_q[(((size_t)(b * HH + h) * NN) + n) * DHH + d] = val;
                } else if (col < 576) {
                    g_k[(size_t)m * DHH + (col - 512)] = val;
                } else {
                    g_v[(size_t)m * DHH + (col - 576)] = val;
                }
            }
}

// K4: [g*local + (1-g)*mem][4096x512] @ Wo[512x512] + bo  (gate combine fused)
extern "C" __global__ __launch_bounds__(256)
void out_proj_kernel(const float* __restrict__ Wo,
                     const float* __restrict__ bo,
                     const float* __restrict__ gate,
                     float* __restrict__ out) {
    __shared__ float Ah[64 * G_LDA], Al[64 * G_LDA];
    __shared__ float Bh[32 * G_LDB], Bl[32 * G_LDB];

    int tid = threadIdx.x;
    int lane = tid & 31, wid = tid >> 5;
    int warpM = wid >> 2, warpN = wid & 3;
    int lr = lane >> 2, lc = lane & 3;
    int n0 = blockIdx.x * 64;
    int m0 = blockIdx.y * 64;

    float acc[2][2][4];
    #pragma unroll
    for (int mi = 0; mi < 2; mi++)
        #pragma unroll
        for (int ni = 0; ni < 2; ni++)
            #pragma unroll
            for (int t = 0; t < 4; t++) acc[mi][ni][t] = 0.f;

    for (int k0 = 0; k0 < DIMM; k0 += 32) {
        __syncthreads();
        // A tile: gate-combined g_local/g_mem
        #pragma unroll
        for (int p = 0; p < 2; p++) {
            int r = (tid >> 3) + p * 32;
            int c = (tid & 7) * 4;
            int m = m0 + r;
            int b = m >> 11, n = m & 2047;
            int col = k0 + c;
            int h = col >> 6, d = col & 63;
            size_t idx = (((size_t)(b * HH + h) * NN) + n) * DHH + d;
            float4 lv = *(const float4*)(g_local + idx);
            float4 mv = *(const float4*)(g_mem + idx);
            float gg = 1.f / (1.f + __expf(-gate[h]));
            float om = 1.f - gg;
            float4 v;
            v.x = lv.x * gg + mv.x * om;
            v.y = lv.y * gg + mv.y * om;
            v.z = lv.z * gg + mv.z * om;
            v.w = lv.w * gg + mv.w * om;
            float h0, l0, h1, l1, h2, l2, h3, l3;
            tf_split(v.x, h0, l0); tf_split(v.y, h1, l1);
            tf_split(v.z, h2, l2); tf_split(v.w, h3, l3);
            float* ph = Ah + r * G_LDA + c;
            float* pl = Al + r * G_LDA + c;
            ph[0] = h0; ph[1] = h1; ph[2] = h2; ph[3] = h3;
            pl[0] = l0; pl[1] = l1; pl[2] = l2; pl[3] = l3;
        }
        #pragma unroll
        for (int p = 0; p < 2; p++) {
            int r = (tid >> 4) + p * 16;
            int c = (tid & 15) * 4;
            float4 v = *(const float4*)(Wo + (size_t)(k0 + r) * DIMM + n0 + c);
            float h0, l0, h1, l1, h2, l2, h3, l3;
            tf_split(v.x, h0, l0); tf_split(v.y, h1, l1);
            tf_split(v.z, h2, l2); tf_split(v.w, h3, l3);
            float* ph = Bh + r * G_LDB + c;
            float* pl = Bl + r * G_LDB + c;
            ph[0] = h0; ph[1] = h1; ph[2] = h2; ph[3] = h3;
            pl[0] = l0; pl[1] = l1; pl[2] = l2; pl[3] = l3;
        }
        __syncthreads();

        #pragma unroll
        for (int kk = 0; kk < 4; kk++) {
            int kc = kk * 8 + lc;
            unsigned ah[2][4], al[2][4];
            #pragma unroll
            for (int mi = 0; mi < 2; mi++) {
                int r = warpM * 32 + mi * 16 + lr;
                ah[mi][0] = __float_as_uint(Ah[r * G_LDA + kc]);
                ah[mi][1] = __float_as_uint(Ah[(r + 8) * G_LDA + kc]);
                ah[mi][2] = __float_as_uint(Ah[r * G_LDA + kc + 4]);
                ah[mi][3] = __float_as_uint(Ah[(r + 8) * G_LDA + kc + 4]);
                al[mi][0] = __float_as_uint(Al[r * G_LDA + kc]);
                al[mi][1] = __float_as_uint(Al[(r + 8) * G_LDA + kc]);
                al[mi][2] = __float_as_uint(Al[r * G_LDA + kc + 4]);
                al[mi][3] = __float_as_uint(Al[(r + 8) * G_LDA + kc + 4]);
            }
            unsigned bh[2][2], bl[2][2];
            #pragma unroll
            for (int ni = 0; ni < 2; ni++) {
                int n = warpN * 16 + ni * 8 + lr;
                bh[ni][0] = __float_as_uint(Bh[kc * G_LDB + n]);
                bh[ni][1] = __float_as_uint(Bh[(kc + 4) * G_LDB + n]);
                bl[ni][0] = __float_as_uint(Bl[kc * G_LDB + n]);
                bl[ni][1] = __float_as_uint(Bl[(kc + 4) * G_LDB + n]);
            }
            #pragma unroll
            for (int mi = 0; mi < 2; mi++)
                #pragma unroll
                for (int ni = 0; ni < 2; ni++) {
                    mma_tf32(acc[mi][ni], ah[mi][0], ah[mi][1], ah[mi][2], ah[mi][3],
                             bh[ni][0], bh[ni][1]);
                    mma_tf32(acc[mi][ni], ah[mi][0], ah[mi][1], ah[mi][2], ah[mi][3],
                             bl[ni][0], bl[ni][1]);
                    mma_tf32(acc[mi][ni], al[mi][0], al[mi][1], al[mi][2], al[mi][3],
                             bh[ni][0], bh[ni][1]);
                }
        }
    }

    #pragma unroll
    for (int mi = 0; mi < 2; mi++)
        #pragma unroll
        for (int ni = 0; ni < 2; ni++)
            #pragma unroll
            for (int t = 0; t < 4; t++) {
                int m = m0 + warpM * 32 + mi * 16 + lr + ((t >= 2) ? 8 : 0);
                int col = n0 + warpN * 16 + ni * 8 + lc * 2 + (t & 1);
                out[(size_t)m * DIMM + col] = acc[mi][ni][t] + bo[col];
            }
}

// ---------------------------------------------------------------------------
// K2: local causal flash attention, tf32 mma, on-the-fly hi/lo split.
// Block = 64 query rows of one (b,h); 4 warps; smem 73.7KB (Q,K raw fp32;
// V,P tf32-valued fp32).  LPT ordering: heavy i0 first.
// ---------------------------------------------------------------------------
#define A_LD 72
#define ATTN_SMEM_FLOATS (4*64*A_LD)

extern "C" __global__ __launch_bounds__(128)
void local_attn_kernel() {
    extern __shared__ float sm[];
    float* Qs = sm;
    float* Ks = Qs + 64 * A_LD;
    float* Vs = Ks + 64 * A_LD;
    float* Ps = Vs + 64 * A_LD;

    int tid = threadIdx.x;
    int lane = tid & 31, warp = tid >> 5;
    int lr = lane >> 2, lc = lane & 3;
    int bh = blockIdx.y;
    int b = bh / HH;
    int i0 = ((int)gridDim.x - 1 - (int)blockIdx.x) * 64;   // LPT: heavy first

    const float* qbase = g_q + (size_t)bh * NN * DHH;
    const float* kbase = g_k + (size_t)b * NN * DHH;
    const float* vbase = g_v + (size_t)b * NN * DHH;

    // load Q tile (raw fp32)
    #pragma unroll
    for (int p = 0; p < 8; p++) {
        int r = (tid >> 4) + p * 8;
        int c = (tid & 15) * 4;
        float4 v = *(const float4*)(qbase + (size_t)(i0 + r) * DHH + c);
        float* pq = Qs + r * A_LD + c;
        pq[0] = v.x; pq[1] = v.y; pq[2] = v.z; pq[3] = v.w;
    }

    float out[8][4];
    #pragma unroll
    for (int ni = 0; ni < 8; ni++)
        #pragma unroll
        for (int t = 0; t < 4; t++) out[ni][t] = 0.f;
    float m0_ = -1e30f, m1_ = -1e30f, l0_ = 0.f, l1_ = 0.f;

    int gi0 = i0 + warp * 16 + lr;
    int gi1 = gi0 + 8;
    int prow = warp * 16 + lr;

    for (int j0 = 0; j0 <= i0; j0 += 64) {
        __syncthreads();
        // K raw fp32, V tf32-valued
        #pragma unroll
        for (int p = 0; p < 8; p++) {
            int r = (tid >> 4) + p * 8;
            int c = (tid & 15) * 4;
            float4 kv = *(const float4*)(kbase + (size_t)(j0 + r) * DHH + c);
            float* pk = Ks + r * A_LD + c;
            pk[0] = kv.x; pk[1] = kv.y; pk[2] = kv.z; pk[3] = kv.w;
            float4 vv = *(const float4*)(vbase + (size_t)(j0 + r) * DHH + c);
            float* pv = Vs + r * A_LD + c;
            pv[0] = tfval(vv.x); pv[1] = tfval(vv.y);
            pv[2] = tfval(vv.z); pv[3] = tfval(vv.w);
        }
        __syncthreads();

        // S = Q K^T (3-term split tf32)
        float s[8][4];
        #pragma unroll
        for (int ni = 0; ni < 8; ni++)
            #pragma unroll
            for (int t = 0; t < 4; t++) s[ni][t] = 0.f;

        #pragma unroll
        for (int kk = 0; kk < 8; kk++) {
            int kc = kk * 8 + lc;
            unsigned ah0, al0, ah1, al1, ah2, al2, ah3, al3;
            tf_split_u(Qs[prow * A_LD + kc],           ah0, al0);
            tf_split_u(Qs[(prow + 8) * A_LD + kc],     ah1, al1);
            tf_split_u(Qs[prow * A_LD + kc + 4],       ah2, al2);
            tf_split_u(Qs[(prow + 8) * A_LD + kc + 4], ah3, al3);
            #pragma unroll
            for (int ni = 0; ni < 8; ni++) {
                int n = ni * 8 + lr;
                unsigned bh0, bl0, bh1, bl1;
                tf_split_u(Ks[n * A_LD + kc],     bh0, bl0);
                tf_split_u(Ks[n * A_LD + kc + 4], bh1, bl1);
                mma_tf32(s[ni], ah0, ah1, ah2, ah3, bh0, bh1);
                mma_tf32(s[ni], ah0, ah1, ah2, ah3, bl0, bl1);
                mma_tf32(s[ni], al0, al1, al2, al3, bh0, bh1);
            }
        }

        // scale + causal mask + row max
        bool diag = (j0 == i0);
        float mx0 = -1e30f, mx1 = -1e30f;
        #pragma unroll
        for (int ni = 0; ni < 8; ni++) {
            int gj = j0 + ni * 8 + lc * 2;
            s[ni][0] *= SCALE; s[ni][1] *= SCALE;
            s[ni][2] *= SCALE; s[ni][3] *= SCALE;
            if (diag) {
                if (gj > gi0)     s[ni][0] = -1e30f;
                if (gj + 1 > gi0) s[ni][1] = -1e30f;
                if (gj > gi1)     s[ni][2] = -1e30f;
                if (gj + 1 > gi1) s[ni][3] = -1e30f;
            }
            mx0 = fmaxf(mx0, fmaxf(s[ni][0], s[ni][1]));
            mx1 = fmaxf(mx1, fmaxf(s[ni][2], s[ni][3]));
        }
        mx0 = fmaxf(mx0, __shfl_xor_sync(0xffffffffu, mx0, 1));
        mx0 = fmaxf(mx0, __shfl_xor_sync(0xffffffffu, mx0, 2));
        mx1 = fmaxf(mx1, __shfl_xor_sync(0xffffffffu, mx1, 1));
        mx1 = fmaxf(mx1, __shfl_xor_sync(0xffffffffu, mx1, 2));

        float mn0 = fmaxf(m0_, mx0), mn1 = fmaxf(m1_, mx1);
        float corr0 = __expf(m0_ - mn0), corr1 = __expf(m1_ - mn1);
        float sum0 = 0.f, sum1 = 0.f;
        #pragma unroll
        for (int ni = 0; ni < 8; ni++) {
            float p0 = __expf(s[ni][0] - mn0);
            float p1 = __expf(s[ni][1] - mn0);
            float p2 = __expf(s[ni][2] - mn1);
            float p3 = __expf(s[ni][3] - mn1);
            sum0 += p0 + p1; sum1 += p2 + p3;
            int c = ni * 8 + lc * 2;
            Ps[prow * A_LD + c]           = tfval(p0);
            Ps[prow * A_LD + c + 1]       = tfval(p1);
            Ps[(prow + 8) * A_LD + c]     = tfval(p2);
            Ps[(prow + 8) * A_LD + c + 1] = tfval(p3);
        }
        sum0 += __shfl_xor_sync(0xffffffffu, sum0, 1);
        sum0 += __shfl_xor_sync(0xffffffffu, sum0, 2);
        sum1 += __shfl_xor_sync(0xffffffffu, sum1, 1);
        sum1 += __shfl_xor_sync(0xffffffffu, sum1, 2);
        l0_ = l0_ * corr0 + sum0;
        l1_ = l1_ * corr1 + sum1;
        m0_ = mn0; m1_ = mn1;

        #pragma unroll
        for (int ni = 0; ni < 8; ni++) {
            out[ni][0] *= corr0; out[ni][1] *= corr0;
            out[ni][2] *= corr1; out[ni][3] *= corr1;
        }
        __syncwarp();

        // out += P @ V  (single tf32)
        #pragma unroll
        for (int kk = 0; kk < 8; kk++) {
            int kc = kk * 8 + lc;
            unsigned pa0 = __float_as_uint(Ps[prow * A_LD + kc]);
            unsigned pa1 = __float_as_uint(Ps[(prow + 8) * A_LD + kc]);
            unsigned pa2 = __float_as_uint(Ps[prow * A_LD + kc + 4]);
            unsigned pa3 = __float_as_uint(Ps[(prow + 8) * A_LD + kc + 4]);
            #pragma unroll
            for (int ni = 0; ni < 8; ni++) {
                int n = ni * 8 + lr;
                unsigned vb0 = __float_as_uint(Vs[kc * A_LD + n]);
                unsigned vb1 = __float_as_uint(Vs[(kc + 4) * A_LD + n]);
                mma_tf32(out[ni], pa0, pa1, pa2, pa3, vb0, vb1);
            }
        }
    }

    float inv0 = 1.f / l0_, inv1 = 1.f / l1_;
    float* lbase = g_local + (size_t)bh * NN * DHH;
    #pragma unroll
    for (int ni = 0; ni < 8; ni++) {
        int c = ni * 8 + lc * 2;
        int r0 = i0 + prow, r1 = r0 + 8;
        lbase[(size_t)r0 * DHH + c]     = out[ni][0] * inv0;
        lbase[(size_t)r0 * DHH + c + 1] = out[ni][1] * inv0;
        lbase[(size_t)r1 * DHH + c]     = out[ni][2] * inv1;
        lbase[(size_t)r1 * DHH + c + 1] = out[ni][3] * inv1;
    }
}

// ---------------------------------------------------------------------------
// K3: memory attention -> g_mem (normalized). Two rows per warp (16-lane
// halves), branch-free masking so loads pipeline across j.
// ---------------------------------------------------------------------------
__global__ void mem_attn_kernel(const float* __restrict__ mem_kv,
                                const float* __restrict__ mem_mask,
                                const float* __restrict__ null_k,
                                const float* __restrict__ null_v) {
    int gw = (blockIdx.x * blockDim.x + threadIdx.x) >> 5;
    int lane = threadIdx.x & 31;
    int half = lane >> 4;          // 0 or 1
    int li = lane & 15;            // lane within half
    int row = gw * 2 + half;       // (b*H+h)*N + i
    if (row >= BB * HH * NN) return;

    float4 q4 = *(const float4*)(g_q + (size_t)row * DHH + li * 4);
    const float* kvbase = mem_kv + (size_t)row * KNN * 2 * DHH;
    const float* maskbase = mem_mask + (size_t)row * KNN;

    float m, l;
    float4 acc;
    {   // null slot, always valid
        float4 k4 = *(const float4*)(null_k + li * 4);
        float part = q4.x * k4.x + q4.y * k4.y + q4.z * k4.z + q4.w * k4.w;
        part += __shfl_xor_sync(0xffffffffu, part, 1);
        part += __shfl_xor_sync(0xffffffffu, part, 2);
        part += __shfl_xor_sync(0xffffffffu, part, 4);
        part += __shfl_xor_sync(0xffffffffu, part, 8);
        m = part * SCALE;
        l = 1.f;
        acc = *(const float4*)(null_v + li * 4);
    }
    #pragma unroll 4
    for (int j = 0; j < KNN; j++) {
        const float* kp = kvbase + (size_t)j * 2 * DHH;
        float4 k4 = *(const float4*)(kp + li * 4);
        float4 v4 = *(const float4*)(kp + DHH + li * 4);
        float maskv = maskbase[j];
        float part = q4.x * k4.x + q4.y * k4.y + q4.z * k4.z + q4.w * k4.w;
        part += __shfl_xor_sync(0xffffffffu, part, 1);
        part += __shfl_xor_sync(0xffffffffu, part, 2);
        part += __shfl_xor_sync(0xffffffffu, part, 4);
        part += __shfl_xor_sync(0xffffffffu, part, 8);
        float s = (maskv != 0.0f) ? part * SCALE : -1e30f;
        float m_new = fmaxf(m, s);
        float corr = __expf(m - m_new);
        float w = __expf(s - m_new);
        l = l * corr + w;
        acc.x = acc.x * corr + w * v4.x;
        acc.y = acc.y * corr + w * v4.y;
        acc.z = acc.z * corr + w * v4.z;
        acc.w = acc.w * corr + w * v4.w;
        m = m_new;
    }
    float inv = 1.f / l;
    float4 oc;
    oc.x = acc.x * inv; oc.y = acc.y * inv;
    oc.z = acc.z * inv; oc.w = acc.w * inv;
    *(float4*)(g_mem + (size_t)row * DHH + li * 4) = oc;
}

// ---------------------------------------------------------------------------
extern "C" void kernel_launch(void* const* d_in, const int* in_sizes, int n_in,
                              void* d_out, int out_size) {
    const float* x        = (const float*)d_in[0];
    const float* mem_kv   = (const float*)d_in[1];
    const float* mem_mask = (const float*)d_in[2];
    const float* Wq       = (const float*)d_in[3];
    const float* Wkv      = (const float*)d_in[4];
    const float* Wo       = (const float*)d_in[5];
    const float* bo       = (const float*)d_in[6];
    const float* null_k   = (const float*)d_in[7];
    const float* null_v   = (const float*)d_in[8];
    const float* gate     = (const float*)d_in[9];
    float* out = (float*)d_out;

    size_t attn_smem = ATTN_SMEM_FLOATS * sizeof(float);
    cudaFuncSetAttribute(local_attn_kernel,
                         cudaFuncAttributeMaxDynamicSharedMemorySize, (int)attn_smem);

    // K1: QKV projection (split tf32, BM=64 -> grid 10 x 64)
    qkv_kernel<<<dim3(10, 64), 256>>>(x, Wq, Wkv);

    // K2: local causal flash attention (tf32 mma, LPT order)
    local_attn_kernel<<<dim3(NN / 64, BB * HH), 128, attn_smem>>>();

    // K3: memory attention -> g_mem (2 rows per warp)
    {
        int nwarps = (BB * HH * NN) / 2;              // 16384
        mem_attn_kernel<<<(nwarps * 32) / 256, 256>>>(mem_kv, mem_mask,
                                                      null_k, null_v);
    }

    // K4: gate combine + output projection + bias (BM=64 -> grid 8 x 64)
    out_proj_kernel<<<dim3(8, 64), 256>>>(Wo, bo, gate, out);
}

// round 17
// speedup vs baseline: 1.9160x; 1.1044x over previous
#include <cuda_runtime.h>
#include <math.h>
#include <stdint.h>

#define BB 2
#define NN 2048
#define DIMM 512
#define HH 8
#define DHH 64
#define KNN 32
#define SCALE 0.125f
#define M_TOT (BB*NN)   // 4096

// Scratch (allocation-free rule: __device__ globals)
__device__ float g_q[BB*HH*NN*DHH];      // (b,h,n,d)
__device__ float g_k[BB*NN*DHH];         // (b,n,d)
__device__ float g_v[BB*NN*DHH];
__device__ float g_local[BB*HH*NN*DHH];  // (b,h,n,d)  normalized local attn
__device__ float g_mem[BB*HH*NN*DHH];    // (b,h,n,d)  normalized mem attn

// ---------------------------------------------------------------------------
// tf32 helpers
// ---------------------------------------------------------------------------
__device__ __forceinline__ unsigned f2tf(float x) {
    unsigned r;
    asm("cvt.rna.tf32.f32 %0, %1;" : "=r"(r) : "f"(x));
    return r;
}
__device__ __forceinline__ float tfval(float x) {
    return __uint_as_float(f2tf(x));
}
__device__ __forceinline__ void mma_tf32(float c[4],
                                         unsigned a0, unsigned a1, unsigned a2, unsigned a3,
                                         unsigned b0, unsigned b1) {
    asm volatile(
        "mma.sync.aligned.m16n8k8.row.col.f32.tf32.tf32.f32 "
        "{%0,%1,%2,%3},{%4,%5,%6,%7},{%8,%9},{%0,%1,%2,%3};"
        : "+f"(c[0]), "+f"(c[1]), "+f"(c[2]), "+f"(c[3])
        : "r"(a0), "r"(a1), "r"(a2), "r"(a3), "r"(b0), "r"(b1));
}
__device__ __forceinline__ void tf_split(float x, float& hi, float& lo) {
    hi = tfval(x);
    lo = tfval(x - hi);
}

// ---------------------------------------------------------------------------
// Split-tf32 GEMM: BM=64, BN=64, BK=32, 256 thr, 8 warps (2 warpM x 4 warpN).
// smem static 36KB: Ah/Al[64*36], Bh/Bl[32*72].
// ---------------------------------------------------------------------------
#define G_LDA 36
#define G_LDB 72

// K1: x[4096x512] @ [Wq | Wkv] -> scatter into g_q / g_k / g_v
extern "C" __global__ __launch_bounds__(256)
void qkv_kernel(const float* __restrict__ x,
                const float* __restrict__ Wq,
                const float* __restrict__ Wkv) {
    __shared__ float Ah[64 * G_LDA], Al[64 * G_LDA];
    __shared__ float Bh[32 * G_LDB], Bl[32 * G_LDB];

    int tid = threadIdx.x;
    int lane = tid & 31, wid = tid >> 5;
    int warpM = wid >> 2, warpN = wid & 3;
    int lr = lane >> 2, lc = lane & 3;
    int n0 = blockIdx.x * 64;
    int m0 = blockIdx.y * 64;

    float acc[2][2][4];
    #pragma unroll
    for (int mi = 0; mi < 2; mi++)
        #pragma unroll
        for (int ni = 0; ni < 2; ni++)
            #pragma unroll
            for (int t = 0; t < 4; t++) acc[mi][ni][t] = 0.f;

    for (int k0 = 0; k0 < DIMM; k0 += 32) {
        __syncthreads();
        // A tile 64x32
        #pragma unroll
        for (int p = 0; p < 2; p++) {
            int r = (tid >> 3) + p * 32;
            int c = (tid & 7) * 4;
            float4 v = *(const float4*)(x + (size_t)(m0 + r) * DIMM + k0 + c);
            float h0, l0, h1, l1, h2, l2, h3, l3;
            tf_split(v.x, h0, l0); tf_split(v.y, h1, l1);
            tf_split(v.z, h2, l2); tf_split(v.w, h3, l3);
            float* ph = Ah + r * G_LDA + c;
            float* pl = Al + r * G_LDA + c;
            ph[0] = h0; ph[1] = h1; ph[2] = h2; ph[3] = h3;
            pl[0] = l0; pl[1] = l1; pl[2] = l2; pl[3] = l3;
        }
        // B tile 32x64 (cols from Wq or Wkv)
        #pragma unroll
        for (int p = 0; p < 2; p++) {
            int r = (tid >> 4) + p * 16;
            int c = (tid & 15) * 4;
            int j = n0 + c;
            float4 v;
            if (j < 512) v = *(const float4*)(Wq + (size_t)(k0 + r) * 512 + j);
            else         v = *(const float4*)(Wkv + (size_t)(k0 + r) * 128 + (j - 512));
            float h0, l0, h1, l1, h2, l2, h3, l3;
            tf_split(v.x, h0, l0); tf_split(v.y, h1, l1);
            tf_split(v.z, h2, l2); tf_split(v.w, h3, l3);
            float* ph = Bh + r * G_LDB + c;
            float* pl = Bl + r * G_LDB + c;
            ph[0] = h0; ph[1] = h1; ph[2] = h2; ph[3] = h3;
            pl[0] = l0; pl[1] = l1; pl[2] = l2; pl[3] = l3;
        }
        __syncthreads();

        #pragma unroll
        for (int kk = 0; kk < 4; kk++) {
            int kc = kk * 8 + lc;
            unsigned ah[2][4], al[2][4];
            #pragma unroll
            for (int mi = 0; mi < 2; mi++) {
                int r = warpM * 32 + mi * 16 + lr;
                ah[mi][0] = __float_as_uint(Ah[r * G_LDA + kc]);
                ah[mi][1] = __float_as_uint(Ah[(r + 8) * G_LDA + kc]);
                ah[mi][2] = __float_as_uint(Ah[r * G_LDA + kc + 4]);
                ah[mi][3] = __float_as_uint(Ah[(r + 8) * G_LDA + kc + 4]);
                al[mi][0] = __float_as_uint(Al[r * G_LDA + kc]);
                al[mi][1] = __float_as_uint(Al[(r + 8) * G_LDA + kc]);
                al[mi][2] = __float_as_uint(Al[r * G_LDA + kc + 4]);
                al[mi][3] = __float_as_uint(Al[(r + 8) * G_LDA + kc + 4]);
            }
            unsigned bh[2][2], bl[2][2];
            #pragma unroll
            for (int ni = 0; ni < 2; ni++) {
                int n = warpN * 16 + ni * 8 + lr;
                bh[ni][0] = __float_as_uint(Bh[kc * G_LDB + n]);
                bh[ni][1] = __float_as_uint(Bh[(kc + 4) * G_LDB + n]);
                bl[ni][0] = __float_as_uint(Bl[kc * G_LDB + n]);
                bl[ni][1] = __float_as_uint(Bl[(kc + 4) * G_LDB + n]);
            }
            #pragma unroll
            for (int mi = 0; mi < 2; mi++)
                #pragma unroll
                for (int ni = 0; ni < 2; ni++) {
                    mma_tf32(acc[mi][ni], ah[mi][0], ah[mi][1], ah[mi][2], ah[mi][3],
                             bh[ni][0], bh[ni][1]);
                    mma_tf32(acc[mi][ni], ah[mi][0], ah[mi][1], ah[mi][2], ah[mi][3],
                             bl[ni][0], bl[ni][1]);
                    mma_tf32(acc[mi][ni], al[mi][0], al[mi][1], al[mi][2], al[mi][3],
                             bh[ni][0], bh[ni][1]);
                }
        }
    }

    #pragma unroll
    for (int mi = 0; mi < 2; mi++)
        #pragma unroll
        for (int ni = 0; ni < 2; ni++)
            #pragma unroll
            for (int t = 0; t < 4; t++) {
                int m = m0 + warpM * 32 + mi * 16 + lr + ((t >= 2) ? 8 : 0);
                int col = n0 + warpN * 16 + ni * 8 + lc * 2 + (t & 1);
                float val = acc[mi][ni][t];
                int b = m >> 11, n = m & 2047;
                if (col < 512) {
                    int h = col >> 6, d = col & 63;
                    g_q[(((size_t)(b * HH + h) * NN) + n) * DHH + d] = val;
                } else if (col < 576) {
                    g_k[(size_t)m * DHH + (col - 512)] = val;
                } else {
                    g_v[(size_t)m * DHH + (col - 576)] = val;
                }
            }
}

// K4: [g*local + (1-g)*mem][4096x512] @ Wo[512x512] + bo  (gate combine fused)
extern "C" __global__ __launch_bounds__(256)
void out_proj_kernel(const float* __restrict__ Wo,
                     const float* __restrict__ bo,
                     const float* __restrict__ gate,
                     float* __restrict__ out) {
    __shared__ float Ah[64 * G_LDA], Al[64 * G_LDA];
    __shared__ float Bh[32 * G_LDB], Bl[32 * G_LDB];

    int tid = threadIdx.x;
    int lane = tid & 31, wid = tid >> 5;
    int warpM = wid >> 2, warpN = wid & 3;
    int lr = lane >> 2, lc = lane & 3;
    int n0 = blockIdx.x * 64;
    int m0 = blockIdx.y * 64;

    float acc[2][2][4];
    #pragma unroll
    for (int mi = 0; mi < 2; mi++)
        #pragma unroll
        for (int ni = 0; ni < 2; ni++)
            #pragma unroll
            for (int t = 0; t < 4; t++) acc[mi][ni][t] = 0.f;

    for (int k0 = 0; k0 < DIMM; k0 += 32) {
        __syncthreads();
        // A tile: gate-combined g_local/g_mem
        #pragma unroll
        for (int p = 0; p < 2; p++) {
            int r = (tid >> 3) + p * 32;
            int c = (tid & 7) * 4;
            int m = m0 + r;
            int b = m >> 11, n = m & 2047;
            int col = k0 + c;
            int h = col >> 6, d = col & 63;
            size_t idx = (((size_t)(b * HH + h) * NN) + n) * DHH + d;
            float4 lv = *(const float4*)(g_local + idx);
            float4 mv = *(const float4*)(g_mem + idx);
            float gg = 1.f / (1.f + __expf(-gate[h]));
            float om = 1.f - gg;
            float4 v;
            v.x = lv.x * gg + mv.x * om;
            v.y = lv.y * gg + mv.y * om;
            v.z = lv.z * gg + mv.z * om;
            v.w = lv.w * gg + mv.w * om;
            float h0, l0, h1, l1, h2, l2, h3, l3;
            tf_split(v.x, h0, l0); tf_split(v.y, h1, l1);
            tf_split(v.z, h2, l2); tf_split(v.w, h3, l3);
            float* ph = Ah + r * G_LDA + c;
            float* pl = Al + r * G_LDA + c;
            ph[0] = h0; ph[1] = h1; ph[2] = h2; ph[3] = h3;
            pl[0] = l0; pl[1] = l1; pl[2] = l2; pl[3] = l3;
        }
        #pragma unroll
        for (int p = 0; p < 2; p++) {
            int r = (tid >> 4) + p * 16;
            int c = (tid & 15) * 4;
            float4 v = *(const float4*)(Wo + (size_t)(k0 + r) * DIMM + n0 + c);
            float h0, l0, h1, l1, h2, l2, h3, l3;
            tf_split(v.x, h0, l0); tf_split(v.y, h1, l1);
            tf_split(v.z, h2, l2); tf_split(v.w, h3, l3);
            float* ph = Bh + r * G_LDB + c;
            float* pl = Bl + r * G_LDB + c;
            ph[0] = h0; ph[1] = h1; ph[2] = h2; ph[3] = h3;
            pl[0] = l0; pl[1] = l1; pl[2] = l2; pl[3] = l3;
        }
        __syncthreads();

        #pragma unroll
        for (int kk = 0; kk < 4; kk++) {
            int kc = kk * 8 + lc;
            unsigned ah[2][4], al[2][4];
            #pragma unroll
            for (int mi = 0; mi < 2; mi++) {
                int r = warpM * 32 + mi * 16 + lr;
                ah[mi][0] = __float_as_uint(Ah[r * G_LDA + kc]);
                ah[mi][1] = __float_as_uint(Ah[(r + 8) * G_LDA + kc]);
                ah[mi][2] = __float_as_uint(Ah[r * G_LDA + kc + 4]);
                ah[mi][3] = __float_as_uint(Ah[(r + 8) * G_LDA + kc + 4]);
                al[mi][0] = __float_as_uint(Al[r * G_LDA + kc]);
                al[mi][1] = __float_as_uint(Al[(r + 8) * G_LDA + kc]);
                al[mi][2] = __float_as_uint(Al[r * G_LDA + kc + 4]);
                al[mi][3] = __float_as_uint(Al[(r + 8) * G_LDA + kc + 4]);
            }
            unsigned bh[2][2], bl[2][2];
            #pragma unroll
            for (int ni = 0; ni < 2; ni++) {
                int n = warpN * 16 + ni * 8 + lr;
                bh[ni][0] = __float_as_uint(Bh[kc * G_LDB + n]);
                bh[ni][1] = __float_as_uint(Bh[(kc + 4) * G_LDB + n]);
                bl[ni][0] = __float_as_uint(Bl[kc * G_LDB + n]);
                bl[ni][1] = __float_as_uint(Bl[(kc + 4) * G_LDB + n]);
            }
            #pragma unroll
            for (int mi = 0; mi < 2; mi++)
                #pragma unroll
                for (int ni = 0; ni < 2; ni++) {
                    mma_tf32(acc[mi][ni], ah[mi][0], ah[mi][1], ah[mi][2], ah[mi][3],
                             bh[ni][0], bh[ni][1]);
                    mma_tf32(acc[mi][ni], ah[mi][0], ah[mi][1], ah[mi][2], ah[mi][3],
                             bl[ni][0], bl[ni][1]);
                    mma_tf32(acc[mi][ni], al[mi][0], al[mi][1], al[mi][2], al[mi][3],
                             bh[ni][0], bh[ni][1]);
                }
        }
    }

    #pragma unroll
    for (int mi = 0; mi < 2; mi++)
        #pragma unroll
        for (int ni = 0; ni < 2; ni++)
            #pragma unroll
            for (int t = 0; t < 4; t++) {
                int m = m0 + warpM * 32 + mi * 16 + lr + ((t >= 2) ? 8 : 0);
                int col = n0 + warpN * 16 + ni * 8 + lc * 2 + (t & 1);
                out[(size_t)m * DIMM + col] = acc[mi][ni][t] + bo[col];
            }
}

// ---------------------------------------------------------------------------
// K2: local causal flash attention, SINGLE tf32 mma for QK^T and PV.
// Q/K/V stored tf32-valued at tile load; inner loops are pure LDS + MMA.
// Block = 64 query rows of one (b,h); 4 warps; smem 73.7KB.  LPT order.
// ---------------------------------------------------------------------------
#define A_LD 72
#define ATTN_SMEM_FLOATS (4*64*A_LD)

extern "C" __global__ __launch_bounds__(128)
void local_attn_kernel() {
    extern __shared__ float sm[];
    float* Qs = sm;
    float* Ks = Qs + 64 * A_LD;
    float* Vs = Ks + 64 * A_LD;
    float* Ps = Vs + 64 * A_LD;

    int tid = threadIdx.x;
    int lane = tid & 31, warp = tid >> 5;
    int lr = lane >> 2, lc = lane & 3;
    int bh = blockIdx.y;
    int b = bh / HH;
    int i0 = ((int)gridDim.x - 1 - (int)blockIdx.x) * 64;   // LPT: heavy first

    const float* qbase = g_q + (size_t)bh * NN * DHH;
    const float* kbase = g_k + (size_t)b * NN * DHH;
    const float* vbase = g_v + (size_t)b * NN * DHH;

    // load Q tile (tf32-valued)
    #pragma unroll
    for (int p = 0; p < 8; p++) {
        int r = (tid >> 4) + p * 8;
        int c = (tid & 15) * 4;
        float4 v = *(const float4*)(qbase + (size_t)(i0 + r) * DHH + c);
        float* pq = Qs + r * A_LD + c;
        pq[0] = tfval(v.x); pq[1] = tfval(v.y);
        pq[2] = tfval(v.z); pq[3] = tfval(v.w);
    }

    float out[8][4];
    #pragma unroll
    for (int ni = 0; ni < 8; ni++)
        #pragma unroll
        for (int t = 0; t < 4; t++) out[ni][t] = 0.f;
    float m0_ = -1e30f, m1_ = -1e30f, l0_ = 0.f, l1_ = 0.f;

    int gi0 = i0 + warp * 16 + lr;
    int gi1 = gi0 + 8;
    int prow = warp * 16 + lr;

    for (int j0 = 0; j0 <= i0; j0 += 64) {
        __syncthreads();
        // K, V tiles (tf32-valued)
        #pragma unroll
        for (int p = 0; p < 8; p++) {
            int r = (tid >> 4) + p * 8;
            int c = (tid & 15) * 4;
            float4 kv = *(const float4*)(kbase + (size_t)(j0 + r) * DHH + c);
            float* pk = Ks + r * A_LD + c;
            pk[0] = tfval(kv.x); pk[1] = tfval(kv.y);
            pk[2] = tfval(kv.z); pk[3] = tfval(kv.w);
            float4 vv = *(const float4*)(vbase + (size_t)(j0 + r) * DHH + c);
            float* pv = Vs + r * A_LD + c;
            pv[0] = tfval(vv.x); pv[1] = tfval(vv.y);
            pv[2] = tfval(vv.z); pv[3] = tfval(vv.w);
        }
        __syncthreads();

        // S = Q K^T (single tf32)
        float s[8][4];
        #pragma unroll
        for (int ni = 0; ni < 8; ni++)
            #pragma unroll
            for (int t = 0; t < 4; t++) s[ni][t] = 0.f;

        #pragma unroll
        for (int kk = 0; kk < 8; kk++) {
            int kc = kk * 8 + lc;
            unsigned a0 = __float_as_uint(Qs[prow * A_LD + kc]);
            unsigned a1 = __float_as_uint(Qs[(prow + 8) * A_LD + kc]);
            unsigned a2 = __float_as_uint(Qs[prow * A_LD + kc + 4]);
            unsigned a3 = __float_as_uint(Qs[(prow + 8) * A_LD + kc + 4]);
            #pragma unroll
            for (int ni = 0; ni < 8; ni++) {
                int n = ni * 8 + lr;
                unsigned b0 = __float_as_uint(Ks[n * A_LD + kc]);
                unsigned b1 = __float_as_uint(Ks[n * A_LD + kc + 4]);
                mma_tf32(s[ni], a0, a1, a2, a3, b0, b1);
            }
        }

        // scale + causal mask + row max
        bool diag = (j0 == i0);
        float mx0 = -1e30f, mx1 = -1e30f;
        #pragma unroll
        for (int ni = 0; ni < 8; ni++) {
            int gj = j0 + ni * 8 + lc * 2;
            s[ni][0] *= SCALE; s[ni][1] *= SCALE;
            s[ni][2] *= SCALE; s[ni][3] *= SCALE;
            if (diag) {
                if (gj > gi0)     s[ni][0] = -1e30f;
                if (gj + 1 > gi0) s[ni][1] = -1e30f;
                if (gj > gi1)     s[ni][2] = -1e30f;
                if (gj + 1 > gi1) s[ni][3] = -1e30f;
            }
            mx0 = fmaxf(mx0, fmaxf(s[ni][0], s[ni][1]));
            mx1 = fmaxf(mx1, fmaxf(s[ni][2], s[ni][3]));
        }
        mx0 = fmaxf(mx0, __shfl_xor_sync(0xffffffffu, mx0, 1));
        mx0 = fmaxf(mx0, __shfl_xor_sync(0xffffffffu, mx0, 2));
        mx1 = fmaxf(mx1, __shfl_xor_sync(0xffffffffu, mx1, 1));
        mx1 = fmaxf(mx1, __shfl_xor_sync(0xffffffffu, mx1, 2));

        float mn0 = fmaxf(m0_, mx0), mn1 = fmaxf(m1_, mx1);
        float corr0 = __expf(m0_ - mn0), corr1 = __expf(m1_ - mn1);
        float sum0 = 0.f, sum1 = 0.f;
        #pragma unroll
        for (int ni = 0; ni < 8; ni++) {
            float p0 = __expf(s[ni][0] - mn0);
            float p1 = __expf(s[ni][1] - mn0);
            float p2 = __expf(s[ni][2] - mn1);
            float p3 = __expf(s[ni][3] - mn1);
            sum0 += p0 + p1; sum1 += p2 + p3;
            int c = ni * 8 + lc * 2;
            Ps[prow * A_LD + c]           = tfval(p0);
            Ps[prow * A_LD + c + 1]       = tfval(p1);
            Ps[(prow + 8) * A_LD + c]     = tfval(p2);
            Ps[(prow + 8) * A_LD + c + 1] = tfval(p3);
        }
        sum0 += __shfl_xor_sync(0xffffffffu, sum0, 1);
        sum0 += __shfl_xor_sync(0xffffffffu, sum0, 2);
        sum1 += __shfl_xor_sync(0xffffffffu, sum1, 1);
        sum1 += __shfl_xor_sync(0xffffffffu, sum1, 2);
        l0_ = l0_ * corr0 + sum0;
        l1_ = l1_ * corr1 + sum1;
        m0_ = mn0; m1_ = mn1;

        #pragma unroll
        for (int ni = 0; ni < 8; ni++) {
            out[ni][0] *= corr0; out[ni][1] *= corr0;
            out[ni][2] *= corr1; out[ni][3] *= corr1;
        }
        __syncwarp();

        // out += P @ V  (single tf32)
        #pragma unroll
        for (int kk = 0; kk < 8; kk++) {
            int kc = kk * 8 + lc;
            unsigned pa0 = __float_as_uint(Ps[prow * A_LD + kc]);
            unsigned pa1 = __float_as_uint(Ps[(prow + 8) * A_LD + kc]);
            unsigned pa2 = __float_as_uint(Ps[prow * A_LD + kc + 4]);
            unsigned pa3 = __float_as_uint(Ps[(prow + 8) * A_LD + kc + 4]);
            #pragma unroll
            for (int ni = 0; ni < 8; ni++) {
                int n = ni * 8 + lr;
                unsigned vb0 = __float_as_uint(Vs[kc * A_LD + n]);
                unsigned vb1 = __float_as_uint(Vs[(kc + 4) * A_LD + n]);
                mma_tf32(out[ni], pa0, pa1, pa2, pa3, vb0, vb1);
            }
        }
    }

    float inv0 = 1.f / l0_, inv1 = 1.f / l1_;
    float* lbase = g_local + (size_t)bh * NN * DHH;
    #pragma unroll
    for (int ni = 0; ni < 8; ni++) {
        int c = ni * 8 + lc * 2;
        int r0 = i0 + prow, r1 = r0 + 8;
        lbase[(size_t)r0 * DHH + c]     = out[ni][0] * inv0;
        lbase[(size_t)r0 * DHH + c + 1] = out[ni][1] * inv0;
        lbase[(size_t)r1 * DHH + c]     = out[ni][2] * inv1;
        lbase[(size_t)r1 * DHH + c + 1] = out[ni][3] * inv1;
    }
}

// ---------------------------------------------------------------------------
// K3: memory attention -> g_mem (normalized). Two rows per warp (16-lane
// halves), branch-free masking so loads pipeline across j.
// ---------------------------------------------------------------------------
__global__ void mem_attn_kernel(const float* __restrict__ mem_kv,
                                const float* __restrict__ mem_mask,
                                const float* __restrict__ null_k,
                                const float* __restrict__ null_v) {
    int gw = (blockIdx.x * blockDim.x + threadIdx.x) >> 5;
    int lane = threadIdx.x & 31;
    int half = lane >> 4;          // 0 or 1
    int li = lane & 15;            // lane within half
    int row = gw * 2 + half;       // (b*H+h)*N + i
    if (row >= BB * HH * NN) return;

    float4 q4 = *(const float4*)(g_q + (size_t)row * DHH + li * 4);
    const float* kvbase = mem_kv + (size_t)row * KNN * 2 * DHH;
    const float* maskbase = mem_mask + (size_t)row * KNN;

    float m, l;
    float4 acc;
    {   // null slot, always valid
        float4 k4 = *(const float4*)(null_k + li * 4);
        float part = q4.x * k4.x + q4.y * k4.y + q4.z * k4.z + q4.w * k4.w;
        part += __shfl_xor_sync(0xffffffffu, part, 1);
        part += __shfl_xor_sync(0xffffffffu, part, 2);
        part += __shfl_xor_sync(0xffffffffu, part, 4);
        part += __shfl_xor_sync(0xffffffffu, part, 8);
        m = part * SCALE;
        l = 1.f;
        acc = *(const float4*)(null_v + li * 4);
    }
    #pragma unroll 4
    for (int j = 0; j < KNN; j++) {
        const float* kp = kvbase + (size_t)j * 2 * DHH;
        float4 k4 = *(const float4*)(kp + li * 4);
        float4 v4 = *(const float4*)(kp + DHH + li * 4);
        float maskv = maskbase[j];
        float part = q4.x * k4.x + q4.y * k4.y + q4.z * k4.z + q4.w * k4.w;
        part += __shfl_xor_sync(0xffffffffu, part, 1);
        part += __shfl_xor_sync(0xffffffffu, part, 2);
        part += __shfl_xor_sync(0xffffffffu, part, 4);
        part += __shfl_xor_sync(0xffffffffu, part, 8);
        float s = (maskv != 0.0f) ? part * SCALE : -1e30f;
        float m_new = fmaxf(m, s);
        float corr = __expf(m - m_new);
        float w = __expf(s - m_new);
        l = l * corr + w;
        acc.x = acc.x * corr + w * v4.x;
        acc.y = acc.y * corr + w * v4.y;
        acc.z = acc.z * corr + w * v4.z;
        acc.w = acc.w * corr + w * v4.w;
        m = m_new;
    }
    float inv = 1.f / l;
    float4 oc;
    oc.x = acc.x * inv; oc.y = acc.y * inv;
    oc.z = acc.z * inv; oc.w = acc.w * inv;
    *(float4*)(g_mem + (size_t)row * DHH + li * 4) = oc;
}

// ---------------------------------------------------------------------------
extern "C" void kernel_launch(void* const* d_in, const int* in_sizes, int n_in,
                              void* d_out, int out_size) {
    const float* x        = (const float*)d_in[0];
    const float* mem_kv   = (const float*)d_in[1];
    const float* mem_mask = (const float*)d_in[2];
    const float* Wq       = (const float*)d_in[3];
    const float* Wkv      = (const float*)d_in[4];
    const float* Wo       = (const float*)d_in[5];
    const float* bo       = (const float*)d_in[6];
    const float* null_k   = (const float*)d_in[7];
    const float* null_v   = (const float*)d_in[8];
    const float* gate     = (const float*)d_in[9];
    float* out = (float*)d_out;

    size_t attn_smem = ATTN_SMEM_FLOATS * sizeof(float);
    cudaFuncSetAttribute(local_attn_kernel,
                         cudaFuncAttributeMaxDynamicSharedMemorySize, (int)attn_smem);

    // K1: QKV projection (split tf32, BM=64 -> grid 10 x 64)
    qkv_kernel<<<dim3(10, 64), 256>>>(x, Wq, Wkv);

    // K2: local causal flash attention (single tf32 mma, LPT order)
    local_attn_kernel<<<dim3(NN / 64, BB * HH), 128, attn_smem>>>();

    // K3: memory attention -> g_mem (2 rows per warp)
    {
        int nwarps = (BB * HH * NN) / 2;              // 16384
        mem_attn_kernel<<<(nwarps * 32) / 256, 256>>>(mem_kv, mem_mask,
                                                      null_k, null_v);
    }

    // K4: gate combine + output projection + bias (BM=64 -> grid 8 x 64)
    out_proj_kernel<<<dim3(8, 64), 256>>>(Wo, bo, gate, out);
}